// round 14
// baseline (speedup 1.0000x reference)
#include <cuda_runtime.h>
#include <cuda_fp16.h>
#include <math.h>
#include <stdint.h>

// ---------------------------------------------------------------------------
// FeedForwardQuantum, round 13: warp tile 64x32 ((m,n)=(2,4) of 8 warps) to
// halve B-fragment LDS duplication (L1 was the binding pipe at 69%).
//   - q in 8 half2 regs (A-frag of GEMM1 for 4 m-frags), whole kernel
//   - GEMM1 per 16-k chunk: 2 x m16n8k8.f16 whose D-frags ARE the m16n8k16
//     A operand; bias=accum init; relu via max.f16x2; af transient (16 regs)
//   - B: unchanged R11 layout (fp16, slot permute + chunk interleave in gmem,
//     XOR-16B-granule swizzle at cp.async dst); consumer LDS.64 per (nf,chunk)
//   - 3-stage cp.async pipeline, BK=64, one barrier per k-tile
// CTA 128x128, 256 thr, 2 CTAs/SM.
// ---------------------------------------------------------------------------

#define E_DIM 512
#define F_DIM 2048
#define BM    128
#define BN    128
#define BK    64
#define NT    256
#define NKT   (F_DIM / BK)        // 32
#define NSTG  3
#define BSTG_BYTES 16384          // 128 rows x 64 halves x 2B per stage
#define SMEM_BYTES (NSTG * BSTG_BYTES)   // 49152 B

__device__ __half g_W2h[(size_t)E_DIM * F_DIM];
__device__ __half g_W1h[(size_t)F_DIM * 8];

__device__ __forceinline__ void mma_f16_k8(float* d, uint32_t a0, uint32_t a1, uint32_t b0) {
    asm volatile(
        "mma.sync.aligned.m16n8k8.row.col.f32.f16.f16.f32 "
        "{%0,%1,%2,%3}, {%4,%5}, {%6}, {%0,%1,%2,%3};\n"
        : "+f"(d[0]), "+f"(d[1]), "+f"(d[2]), "+f"(d[3])
        : "r"(a0), "r"(a1), "r"(b0));
}

__device__ __forceinline__ void mma_f16_k16(float* d, const uint32_t* a,
                                            uint32_t b0, uint32_t b1) {
    asm volatile(
        "mma.sync.aligned.m16n8k16.row.col.f32.f16.f16.f32 "
        "{%0,%1,%2,%3}, {%4,%5,%6,%7}, {%8,%9}, {%0,%1,%2,%3};\n"
        : "+f"(d[0]), "+f"(d[1]), "+f"(d[2]), "+f"(d[3])
        : "r"(a[0]), "r"(a[1]), "r"(a[2]), "r"(a[3]), "r"(b0), "r"(b1));
}

__device__ __forceinline__ uint32_t relu_pack(float lo, float hi) {
    uint32_t r;
    asm("cvt.rn.f16x2.f32 %0, %2, %1;" : "=r"(r) : "f"(lo), "f"(hi));
    uint32_t z = 0;
    asm("max.f16x2 %0, %0, %1;" : "+r"(r) : "r"(z));
    return r;
}

__device__ __forceinline__ void cp16(uint32_t dst, const void* src) {
    asm volatile("cp.async.cg.shared.global [%0], [%1], 16;" :: "r"(dst), "l"(src) : "memory");
}

// prep: W2 -> fp16 with slot permute [2fc,2fc+1,2fc+8,2fc+9] and chunk-pair
// interleave baked in (identical to R11); W1 -> fp16 plain.
__global__ void prep_kernel(const float* __restrict__ W2, const float* __restrict__ W1) {
    int idx = blockIdx.x * 256 + threadIdx.x;
    if (idx < E_DIM * F_DIM) {
        int n  = idx >> 11;
        int jg = idx & 2047;
        int t   = jg >> 6;
        int jl  = jg & 63;
        int P   = jl >> 5;
        int fc  = (jl >> 3) & 3;
        int c01 = (jl >> 2) & 1;
        int e   = jl & 3;
        int k = t * 64 + (P * 2 + c01) * 16 + 2 * fc + (e & 1) + ((e >> 1) << 3);
        g_W2h[idx] = __float2half(W2[((size_t)n << 11) + k]);
    } else {
        int i = idx - E_DIM * F_DIM;
        g_W1h[i] = __float2half(W1[i]);
    }
}

__global__ void __launch_bounds__(NT, 2)
ffq_mma_kernel(const float* __restrict__ x, const float* __restrict__ theta,
               const float* __restrict__ b1, const float* __restrict__ b2,
               float* __restrict__ out)
{
    extern __shared__ __half smh[];
    const uint32_t smB_u32 = (uint32_t)__cvta_generic_to_shared(smh);

    const int tid  = threadIdx.x;
    const int lane = tid & 31;
    const int wid  = tid >> 5;
    const int m0   = blockIdx.y * BM;
    const int n0   = blockIdx.x * BN;

    // warp tile 64(M) x 32(N): (m,n) = (2,4) arrangement
    const int mw = (wid & 1) * 64;
    const int nw = (wid >> 1) * 32;
    const int fr = lane >> 2;
    const int fc = lane & 3;

    // ---- q A-fragments: 4 m-frags x 2 half2 regs, whole kernel ----
    uint32_t qa[4][2];
    {
        float tc0 = cosf(__ldg(theta + 2 * fc));
        float tc1 = cosf(__ldg(theta + 2 * fc + 1));
#pragma unroll
        for (int mf = 0; mf < 4; mf++) {
            const float* x0 = x + (size_t)(m0 + mw + mf * 16 + fr) * E_DIM;
            const float* x1 = x0 + (size_t)8 * E_DIM;
            float q00 = cosf(__ldg(x0 + 2 * fc))     * tc0;
            float q01 = cosf(__ldg(x0 + 2 * fc + 1)) * tc1;
            float q10 = cosf(__ldg(x1 + 2 * fc))     * tc0;
            float q11 = cosf(__ldg(x1 + 2 * fc + 1)) * tc1;
            asm("cvt.rn.f16x2.f32 %0, %2, %1;" : "=r"(qa[mf][0]) : "f"(q00), "f"(q01));
            asm("cvt.rn.f16x2.f32 %0, %2, %1;" : "=r"(qa[mf][1]) : "f"(q10), "f"(q11));
        }
    }

    // ---- cp.async bases (unchanged from R11) ----
    const char* w2src = (const char*)g_W2h
                      + (size_t)(n0 + (tid >> 3)) * F_DIM * 2 + (tid & 7) * 16;
    const int dg = (tid & 7) ^ ((tid >> 3) & 7);
    const uint32_t dstbase = smB_u32 + (uint32_t)((tid >> 3) * 128 + dg * 16);

#define ISSUE_B(kt)                                                              \
    do {                                                                         \
        const uint32_t dd = dstbase + (uint32_t)((kt) % NSTG) * BSTG_BYTES;      \
        const char* ss = w2src + (size_t)(kt) * 128;                             \
        cp16(dd,          ss);                                                   \
        cp16(dd + 4096,   ss + (size_t)32 * F_DIM * 2);                          \
        cp16(dd + 8192,   ss + (size_t)64 * F_DIM * 2);                          \
        cp16(dd + 12288,  ss + (size_t)96 * F_DIM * 2);                          \
        asm volatile("cp.async.commit_group;" ::: "memory");                     \
    } while (0)

    ISSUE_B(0);
    ISSUE_B(1);

    float d[4][4][4];
#pragma unroll
    for (int mf = 0; mf < 4; mf++)
#pragma unroll
        for (int nf = 0; nf < 4; nf++)
#pragma unroll
            for (int i = 0; i < 4; i++)
                d[mf][nf][i] = 0.0f;

    for (int kt = 0; kt < NKT; kt++) {
        asm volatile("cp.async.wait_group 1;" ::: "memory");
        __syncthreads();

        if (kt + 2 < NKT) {
            ISSUE_B(kt + 2);
        } else {
            asm volatile("cp.async.commit_group;" ::: "memory");   // keep count
        }

        const __half* B = smh + (kt % NSTG) * (BSTG_BYTES / 2);
        const int f0 = kt * BK;

#pragma unroll
        for (int P = 0; P < 2; P++) {
            // 16B-granule base for this (P, fc) with XOR-row swizzle
            const int gr = (((P * 4) + fc) ^ fr) * 8;     // in halves
#pragma unroll
            for (int c01 = 0; c01 < 2; c01++) {
                // ---- GEMM1: A-fragments for chunk (P, c01), all 4 m-frags ----
                const int kb = f0 + (P * 2 + c01) * 16;
                uint32_t af[4][4];
#pragma unroll
                for (int fb2 = 0; fb2 < 2; fb2++) {
                    const int fb = kb + fb2 * 8;
                    uint32_t w1f = __ldg((const uint32_t*)(g_W1h + (size_t)(fb + fr) * 8 + 2 * fc));
                    float2 bi = *(const float2*)(b1 + fb + 2 * fc);
#pragma unroll
                    for (int mf = 0; mf < 4; mf++) {
                        float dh[4] = {bi.x, bi.y, bi.x, bi.y};
                        mma_f16_k8(dh, qa[mf][0], qa[mf][1], w1f);
                        af[mf][fb2 * 2 + 0] = relu_pack(dh[0], dh[1]);   // row fr
                        af[mf][fb2 * 2 + 1] = relu_pack(dh[2], dh[3]);   // row fr+8
                    }
                }

                // ---- GEMM2 for this chunk ----
#pragma unroll
                for (int nf = 0; nf < 4; nf++) {
                    uint2 vb = *(const uint2*)(B + (nw + nf * 8 + fr) * 64 + gr + c01 * 4);
#pragma unroll
                    for (int mf = 0; mf < 4; mf++)
                        mma_f16_k16(d[mf][nf], af[mf], vb.x, vb.y);
                }
            }
        }
    }

    // ---- epilogue: out = d + b2 ----
    float b2v[4][2];
#pragma unroll
    for (int nf = 0; nf < 4; nf++) {
        b2v[nf][0] = __ldg(b2 + n0 + nw + nf * 8 + fc * 2);
        b2v[nf][1] = __ldg(b2 + n0 + nw + nf * 8 + fc * 2 + 1);
    }
#pragma unroll
    for (int mf = 0; mf < 4; mf++) {
#pragma unroll
        for (int i2 = 0; i2 < 2; i2++) {
            const int row = m0 + mw + mf * 16 + fr + i2 * 8;
            float* orow = out + (size_t)row * E_DIM + n0 + nw + fc * 2;
#pragma unroll
            for (int nf = 0; nf < 4; nf++) {
                float2 v;
                v.x = d[mf][nf][i2 * 2 + 0] + b2v[nf][0];
                v.y = d[mf][nf][i2 * 2 + 1] + b2v[nf][1];
                *(float2*)(orow + nf * 8) = v;
            }
        }
    }
}

extern "C" void kernel_launch(void* const* d_in, const int* in_sizes, int n_in,
                              void* d_out, int out_size) {
    const float* x     = (const float*)d_in[0];
    const float* theta = (const float*)d_in[1];
    const float* W1    = (const float*)d_in[2];
    const float* b1    = (const float*)d_in[3];
    const float* W2    = (const float*)d_in[4];
    const float* b2    = (const float*)d_in[5];
    float* out = (float*)d_out;

    const int M = in_sizes[0] / E_DIM;   // 32768

    prep_kernel<<<(E_DIM * F_DIM + F_DIM * 8) / 256, 256>>>(W2, W1);

    cudaFuncSetAttribute(ffq_mma_kernel,
                         cudaFuncAttributeMaxDynamicSharedMemorySize, SMEM_BYTES);
    dim3 grid(E_DIM / BN, M / BM);
    ffq_mma_kernel<<<grid, NT, SMEM_BYTES>>>(x, theta, b1, b2, out);
}

// round 15
// speedup vs baseline: 1.2789x; 1.2789x over previous
#include <cuda_runtime.h>
#include <cuda_fp16.h>
#include <math.h>
#include <stdint.h>

// ---------------------------------------------------------------------------
// FeedForwardQuantum, round 14: R11 structure (fp16 m16n8k16, warp tile
// 32x64, (m,n)=(4,2)) + 2-tile super-iterations so warps drift and the
// tensor pipe stays fed during other warps' GEMM1/cvt/LDS phases.
//   protocol per super-iter S: wait_group 2 (own tiles S,S+1 arrived)
//   -> __syncthreads (cross-thread visibility) -> issue tiles S+4,S+5
//   -> compute tiles S, S+1 with NO barrier. NSTG=6 keeps all in-flight
//   stages distinct. 16 barriers instead of 32.
// CTA 128x128, 256 thr, 8 warps, 2 CTAs/SM (reg-bound).
// ---------------------------------------------------------------------------

#define E_DIM 512
#define F_DIM 2048
#define BM    128
#define BN    128
#define BK    64
#define NT    256
#define NKT   (F_DIM / BK)        // 32
#define NSTG  6
#define BSTG_BYTES 16384          // 128 rows x 64 halves x 2B per stage
#define SMEM_BYTES (NSTG * BSTG_BYTES)   // 98304 B

__device__ __half g_W2h[(size_t)E_DIM * F_DIM];
__device__ __half g_W1h[(size_t)F_DIM * 8];

__device__ __forceinline__ void mma_f16_k8(float* d, uint32_t a0, uint32_t a1, uint32_t b0) {
    asm volatile(
        "mma.sync.aligned.m16n8k8.row.col.f32.f16.f16.f32 "
        "{%0,%1,%2,%3}, {%4,%5}, {%6}, {%0,%1,%2,%3};\n"
        : "+f"(d[0]), "+f"(d[1]), "+f"(d[2]), "+f"(d[3])
        : "r"(a0), "r"(a1), "r"(b0));
}

__device__ __forceinline__ void mma_f16_k16(float* d, const uint32_t* a,
                                            uint32_t b0, uint32_t b1) {
    asm volatile(
        "mma.sync.aligned.m16n8k16.row.col.f32.f16.f16.f32 "
        "{%0,%1,%2,%3}, {%4,%5,%6,%7}, {%8,%9}, {%0,%1,%2,%3};\n"
        : "+f"(d[0]), "+f"(d[1]), "+f"(d[2]), "+f"(d[3])
        : "r"(a[0]), "r"(a[1]), "r"(a[2]), "r"(a[3]), "r"(b0), "r"(b1));
}

__device__ __forceinline__ uint32_t relu_pack(float lo, float hi) {
    uint32_t r;
    asm("cvt.rn.f16x2.f32 %0, %2, %1;" : "=r"(r) : "f"(lo), "f"(hi));
    uint32_t z = 0;
    asm("max.f16x2 %0, %0, %1;" : "+r"(r) : "r"(z));
    return r;
}

__device__ __forceinline__ void cp16(uint32_t dst, const void* src) {
    asm volatile("cp.async.cg.shared.global [%0], [%1], 16;" :: "r"(dst), "l"(src) : "memory");
}

// prep: W2 -> fp16 with slot permute [2fc,2fc+1,2fc+8,2fc+9] and chunk-pair
// interleave baked in (identical to R11); W1 -> fp16 plain.
__global__ void prep_kernel(const float* __restrict__ W2, const float* __restrict__ W1) {
    int idx = blockIdx.x * 256 + threadIdx.x;
    if (idx < E_DIM * F_DIM) {
        int n  = idx >> 11;
        int jg = idx & 2047;
        int t   = jg >> 6;
        int jl  = jg & 63;
        int P   = jl >> 5;
        int fc  = (jl >> 3) & 3;
        int c01 = (jl >> 2) & 1;
        int e   = jl & 3;
        int k = t * 64 + (P * 2 + c01) * 16 + 2 * fc + (e & 1) + ((e >> 1) << 3);
        g_W2h[idx] = __float2half(W2[((size_t)n << 11) + k]);
    } else {
        int i = idx - E_DIM * F_DIM;
        g_W1h[i] = __float2half(W1[i]);
    }
}

__global__ void __launch_bounds__(NT, 2)
ffq_mma_kernel(const float* __restrict__ x, const float* __restrict__ theta,
               const float* __restrict__ b1, const float* __restrict__ b2,
               float* __restrict__ out)
{
    extern __shared__ __half smh[];
    const uint32_t smB_u32 = (uint32_t)__cvta_generic_to_shared(smh);

    const int tid  = threadIdx.x;
    const int lane = tid & 31;
    const int wid  = tid >> 5;
    const int m0   = blockIdx.y * BM;
    const int n0   = blockIdx.x * BN;

    // warp tile 32(M) x 64(N): (m,n) = (4,2)   [R11 arrangement]
    const int mw = (wid & 3) * 32;
    const int nw = (wid >> 2) * 64;
    const int fr = lane >> 2;
    const int fc = lane & 3;

    // ---- q A-fragments (half2 pairs, whole kernel) ----
    uint32_t qa[2][2];
    {
        float tc0 = cosf(__ldg(theta + 2 * fc));
        float tc1 = cosf(__ldg(theta + 2 * fc + 1));
#pragma unroll
        for (int mf = 0; mf < 2; mf++) {
            const float* x0 = x + (size_t)(m0 + mw + mf * 16 + fr) * E_DIM;
            const float* x1 = x0 + (size_t)8 * E_DIM;
            float q00 = cosf(__ldg(x0 + 2 * fc))     * tc0;
            float q01 = cosf(__ldg(x0 + 2 * fc + 1)) * tc1;
            float q10 = cosf(__ldg(x1 + 2 * fc))     * tc0;
            float q11 = cosf(__ldg(x1 + 2 * fc + 1)) * tc1;
            asm("cvt.rn.f16x2.f32 %0, %2, %1;" : "=r"(qa[mf][0]) : "f"(q00), "f"(q01));
            asm("cvt.rn.f16x2.f32 %0, %2, %1;" : "=r"(qa[mf][1]) : "f"(q10), "f"(q11));
        }
    }

    // ---- cp.async bases: row = (tid>>3) + 32j, 16B granule = tid&7 ----
    const char* w2src = (const char*)g_W2h
                      + (size_t)(n0 + (tid >> 3)) * F_DIM * 2 + (tid & 7) * 16;
    const int dg = (tid & 7) ^ ((tid >> 3) & 7);
    const uint32_t dstbase = smB_u32 + (uint32_t)((tid >> 3) * 128 + dg * 16);

#define ISSUE_B(kt)                                                              \
    do {                                                                         \
        const uint32_t dd = dstbase + (uint32_t)((kt) % NSTG) * BSTG_BYTES;      \
        const char* ss = w2src + (size_t)(kt) * 128;                             \
        cp16(dd,          ss);                                                   \
        cp16(dd + 4096,   ss + (size_t)32 * F_DIM * 2);                          \
        cp16(dd + 8192,   ss + (size_t)64 * F_DIM * 2);                          \
        cp16(dd + 12288,  ss + (size_t)96 * F_DIM * 2);                          \
        asm volatile("cp.async.commit_group;" ::: "memory");                     \
    } while (0)

    ISSUE_B(0);
    ISSUE_B(1);
    ISSUE_B(2);
    ISSUE_B(3);

    float d[2][8][4];
#pragma unroll
    for (int mf = 0; mf < 2; mf++)
#pragma unroll
        for (int nf = 0; nf < 8; nf++)
#pragma unroll
            for (int i = 0; i < 4; i++)
                d[mf][nf][i] = 0.0f;

    // one k-tile of compute over stage kt%NSTG (identical math to R11)
    auto compute_tile = [&](int kt) {
        const __half* B = smh + (kt % NSTG) * (BSTG_BYTES / 2);
        const int f0 = kt * BK;
#pragma unroll
        for (int P = 0; P < 2; P++) {
            // ---- GEMM1: A-fragments for chunks 2P, 2P+1 ----
            uint32_t af[2][2][4];   // [c01][mf][R0..R3]
#pragma unroll
            for (int c01 = 0; c01 < 2; c01++) {
                const int kb = f0 + (P * 2 + c01) * 16;
#pragma unroll
                for (int fb2 = 0; fb2 < 2; fb2++) {
                    const int fb = kb + fb2 * 8;
                    uint32_t w1f = __ldg((const uint32_t*)(g_W1h + (size_t)(fb + fr) * 8 + 2 * fc));
                    float2 bi = *(const float2*)(b1 + fb + 2 * fc);
#pragma unroll
                    for (int mf = 0; mf < 2; mf++) {
                        float dh[4] = {bi.x, bi.y, bi.x, bi.y};
                        mma_f16_k8(dh, qa[mf][0], qa[mf][1], w1f);
                        af[c01][mf][fb2 * 2 + 0] = relu_pack(dh[0], dh[1]);   // row fr
                        af[c01][mf][fb2 * 2 + 1] = relu_pack(dh[2], dh[3]);   // row fr+8
                    }
                }
            }
            // ---- GEMM2 over chunk pair P ----
            const int gr = (((P * 4) + fc) ^ fr) * 8;    // halves (16B granule)
#pragma unroll
            for (int nf = 0; nf < 8; nf++) {
                uint4 vb = *(const uint4*)(B + (nw + nf * 8 + fr) * 64 + gr);
#pragma unroll
                for (int mf = 0; mf < 2; mf++) {
                    mma_f16_k16(d[mf][nf], af[0][mf], vb.x, vb.y);
                    mma_f16_k16(d[mf][nf], af[1][mf], vb.z, vb.w);
                }
            }
        }
    };

    // ---- mainloop: 2 k-tiles per super-iteration ----
    for (int S = 0; S < NKT; S += 2) {
        // own tiles S, S+1 arrived (committed S+4 groups so far, pending <= 2)
        asm volatile("cp.async.wait_group 2;" ::: "memory");
        // every thread has waited -> barrier makes all copies visible to all
        __syncthreads();

        if (S + 4 < NKT) { ISSUE_B(S + 4); }
        else { asm volatile("cp.async.commit_group;" ::: "memory"); }
        if (S + 5 < NKT) { ISSUE_B(S + 5); }
        else { asm volatile("cp.async.commit_group;" ::: "memory"); }

        compute_tile(S);
        compute_tile(S + 1);
    }

    // ---- epilogue: out = d + b2 ----
    float b2v[8][2];
#pragma unroll
    for (int nf = 0; nf < 8; nf++) {
        b2v[nf][0] = __ldg(b2 + n0 + nw + nf * 8 + fc * 2);
        b2v[nf][1] = __ldg(b2 + n0 + nw + nf * 8 + fc * 2 + 1);
    }
#pragma unroll
    for (int mf = 0; mf < 2; mf++) {
#pragma unroll
        for (int i2 = 0; i2 < 2; i2++) {
            const int row = m0 + mw + mf * 16 + fr + i2 * 8;
            float* orow = out + (size_t)row * E_DIM + n0 + nw + fc * 2;
#pragma unroll
            for (int nf = 0; nf < 8; nf++) {
                float2 v;
                v.x = d[mf][nf][i2 * 2 + 0] + b2v[nf][0];
                v.y = d[mf][nf][i2 * 2 + 1] + b2v[nf][1];
                *(float2*)(orow + nf * 8) = v;
            }
        }
    }
}

extern "C" void kernel_launch(void* const* d_in, const int* in_sizes, int n_in,
                              void* d_out, int out_size) {
    const float* x     = (const float*)d_in[0];
    const float* theta = (const float*)d_in[1];
    const float* W1    = (const float*)d_in[2];
    const float* b1    = (const float*)d_in[3];
    const float* W2    = (const float*)d_in[4];
    const float* b2    = (const float*)d_in[5];
    float* out = (float*)d_out;

    const int M = in_sizes[0] / E_DIM;   // 32768

    prep_kernel<<<(E_DIM * F_DIM + F_DIM * 8) / 256, 256>>>(W2, W1);

    cudaFuncSetAttribute(ffq_mma_kernel,
                         cudaFuncAttributeMaxDynamicSharedMemorySize, SMEM_BYTES);
    dim3 grid(E_DIM / BN, M / BM);
    ffq_mma_kernel<<<grid, NT, SMEM_BYTES>>>(x, theta, b1, b2, out);
}

// round 16
// speedup vs baseline: 1.3777x; 1.0772x over previous
#include <cuda_runtime.h>
#include <cuda_fp16.h>
#include <math.h>
#include <stdint.h>

// ---------------------------------------------------------------------------
// FeedForwardQuantum, round 15: R14 kernel + conflict-free B-fragment swizzle.
//   Old granule map  (s ^ fr) left phase row-pairs on the SAME 4 granules
//   -> 2-way bank conflict on every LDS.128 phase. New map
//   pi(s, r) = s ^ (r&6) ^ ((r&1)<<2) gives even/odd rows complementary
//   granule halves -> each phase covers all 32 banks once (conflict-free).
//   Producer cp.async dst uses the same map; everything else identical.
// CTA 128x128, 256 thr, 8 warps (warp tile 32x64), NSTG=6, 2-tile superiter.
// ---------------------------------------------------------------------------

#define E_DIM 512
#define F_DIM 2048
#define BM    128
#define BN    128
#define BK    64
#define NT    256
#define NKT   (F_DIM / BK)        // 32
#define NSTG  6
#define BSTG_BYTES 16384          // 128 rows x 64 halves x 2B per stage
#define SMEM_BYTES (NSTG * BSTG_BYTES)   // 98304 B

__device__ __half g_W2h[(size_t)E_DIM * F_DIM];
__device__ __half g_W1h[(size_t)F_DIM * 8];

__device__ __forceinline__ void mma_f16_k8(float* d, uint32_t a0, uint32_t a1, uint32_t b0) {
    asm volatile(
        "mma.sync.aligned.m16n8k8.row.col.f32.f16.f16.f32 "
        "{%0,%1,%2,%3}, {%4,%5}, {%6}, {%0,%1,%2,%3};\n"
        : "+f"(d[0]), "+f"(d[1]), "+f"(d[2]), "+f"(d[3])
        : "r"(a0), "r"(a1), "r"(b0));
}

__device__ __forceinline__ void mma_f16_k16(float* d, const uint32_t* a,
                                            uint32_t b0, uint32_t b1) {
    asm volatile(
        "mma.sync.aligned.m16n8k16.row.col.f32.f16.f16.f32 "
        "{%0,%1,%2,%3}, {%4,%5,%6,%7}, {%8,%9}, {%0,%1,%2,%3};\n"
        : "+f"(d[0]), "+f"(d[1]), "+f"(d[2]), "+f"(d[3])
        : "r"(a[0]), "r"(a[1]), "r"(a[2]), "r"(a[3]), "r"(b0), "r"(b1));
}

__device__ __forceinline__ uint32_t relu_pack(float lo, float hi) {
    uint32_t r;
    asm("cvt.rn.f16x2.f32 %0, %2, %1;" : "=r"(r) : "f"(lo), "f"(hi));
    uint32_t z = 0;
    asm("max.f16x2 %0, %0, %1;" : "+r"(r) : "r"(z));
    return r;
}

__device__ __forceinline__ void cp16(uint32_t dst, const void* src) {
    asm volatile("cp.async.cg.shared.global [%0], [%1], 16;" :: "r"(dst), "l"(src) : "memory");
}

// prep: W2 -> fp16 with slot permute [2fc,2fc+1,2fc+8,2fc+9] and chunk-pair
// interleave baked in (unchanged); W1 -> fp16 plain.
__global__ void prep_kernel(const float* __restrict__ W2, const float* __restrict__ W1) {
    int idx = blockIdx.x * 256 + threadIdx.x;
    if (idx < E_DIM * F_DIM) {
        int n  = idx >> 11;
        int jg = idx & 2047;
        int t   = jg >> 6;
        int jl  = jg & 63;
        int P   = jl >> 5;
        int fc  = (jl >> 3) & 3;
        int c01 = (jl >> 2) & 1;
        int e   = jl & 3;
        int k = t * 64 + (P * 2 + c01) * 16 + 2 * fc + (e & 1) + ((e >> 1) << 3);
        g_W2h[idx] = __float2half(W2[((size_t)n << 11) + k]);
    } else {
        int i = idx - E_DIM * F_DIM;
        g_W1h[i] = __float2half(W1[i]);
    }
}

__global__ void __launch_bounds__(NT, 2)
ffq_mma_kernel(const float* __restrict__ x, const float* __restrict__ theta,
               const float* __restrict__ b1, const float* __restrict__ b2,
               float* __restrict__ out)
{
    extern __shared__ __half smh[];
    const uint32_t smB_u32 = (uint32_t)__cvta_generic_to_shared(smh);

    const int tid  = threadIdx.x;
    const int lane = tid & 31;
    const int wid  = tid >> 5;
    const int m0   = blockIdx.y * BM;
    const int n0   = blockIdx.x * BN;

    // warp tile 32(M) x 64(N): (m,n) = (4,2)
    const int mw = (wid & 3) * 32;
    const int nw = (wid >> 2) * 64;
    const int fr = lane >> 2;
    const int fc = lane & 3;
    // parity-disjoint swizzle constant for this thread's fragment row
    const int swc = (fr & 6) ^ ((fr & 1) << 2);

    // ---- q A-fragments (half2 pairs, whole kernel) ----
    uint32_t qa[2][2];
    {
        float tc0 = cosf(__ldg(theta + 2 * fc));
        float tc1 = cosf(__ldg(theta + 2 * fc + 1));
#pragma unroll
        for (int mf = 0; mf < 2; mf++) {
            const float* x0 = x + (size_t)(m0 + mw + mf * 16 + fr) * E_DIM;
            const float* x1 = x0 + (size_t)8 * E_DIM;
            float q00 = cosf(__ldg(x0 + 2 * fc))     * tc0;
            float q01 = cosf(__ldg(x0 + 2 * fc + 1)) * tc1;
            float q10 = cosf(__ldg(x1 + 2 * fc))     * tc0;
            float q11 = cosf(__ldg(x1 + 2 * fc + 1)) * tc1;
            asm("cvt.rn.f16x2.f32 %0, %2, %1;" : "=r"(qa[mf][0]) : "f"(q00), "f"(q01));
            asm("cvt.rn.f16x2.f32 %0, %2, %1;" : "=r"(qa[mf][1]) : "f"(q10), "f"(q11));
        }
    }

    // ---- cp.async bases: row = (tid>>3) + 32j, 16B granule = tid&7 ----
    const char* w2src = (const char*)g_W2h
                      + (size_t)(n0 + (tid >> 3)) * F_DIM * 2 + (tid & 7) * 16;
    const int row8 = (tid >> 3) & 7;
    const int dg = (tid & 7) ^ (row8 & 6) ^ ((row8 & 1) << 2);
    const uint32_t dstbase = smB_u32 + (uint32_t)((tid >> 3) * 128 + dg * 16);

#define ISSUE_B(kt)                                                              \
    do {                                                                         \
        const uint32_t dd = dstbase + (uint32_t)((kt) % NSTG) * BSTG_BYTES;      \
        const char* ss = w2src + (size_t)(kt) * 128;                             \
        cp16(dd,          ss);                                                   \
        cp16(dd + 4096,   ss + (size_t)32 * F_DIM * 2);                          \
        cp16(dd + 8192,   ss + (size_t)64 * F_DIM * 2);                          \
        cp16(dd + 12288,  ss + (size_t)96 * F_DIM * 2);                          \
        asm volatile("cp.async.commit_group;" ::: "memory");                     \
    } while (0)

    ISSUE_B(0);
    ISSUE_B(1);
    ISSUE_B(2);
    ISSUE_B(3);

    float d[2][8][4];
#pragma unroll
    for (int mf = 0; mf < 2; mf++)
#pragma unroll
        for (int nf = 0; nf < 8; nf++)
#pragma unroll
            for (int i = 0; i < 4; i++)
                d[mf][nf][i] = 0.0f;

    // one k-tile of compute over stage kt%NSTG
    auto compute_tile = [&](int kt) {
        const __half* B = smh + (kt % NSTG) * (BSTG_BYTES / 2);
        const int f0 = kt * BK;
#pragma unroll
        for (int P = 0; P < 2; P++) {
            // ---- GEMM1: A-fragments for chunks 2P, 2P+1 ----
            uint32_t af[2][2][4];   // [c01][mf][R0..R3]
#pragma unroll
            for (int c01 = 0; c01 < 2; c01++) {
                const int kb = f0 + (P * 2 + c01) * 16;
#pragma unroll
                for (int fb2 = 0; fb2 < 2; fb2++) {
                    const int fb = kb + fb2 * 8;
                    uint32_t w1f = __ldg((const uint32_t*)(g_W1h + (size_t)(fb + fr) * 8 + 2 * fc));
                    float2 bi = *(const float2*)(b1 + fb + 2 * fc);
#pragma unroll
                    for (int mf = 0; mf < 2; mf++) {
                        float dh[4] = {bi.x, bi.y, bi.x, bi.y};
                        mma_f16_k8(dh, qa[mf][0], qa[mf][1], w1f);
                        af[c01][mf][fb2 * 2 + 0] = relu_pack(dh[0], dh[1]);   // row fr
                        af[c01][mf][fb2 * 2 + 1] = relu_pack(dh[2], dh[3]);   // row fr+8
                    }
                }
            }
            // ---- GEMM2 over chunk pair P (conflict-free granule map) ----
            const int gr = (((P * 4) + fc) ^ swc) * 8;    // halves (16B granule)
#pragma unroll
            for (int nf = 0; nf < 8; nf++) {
                uint4 vb = *(const uint4*)(B + (nw + nf * 8 + fr) * 64 + gr);
#pragma unroll
                for (int mf = 0; mf < 2; mf++) {
                    mma_f16_k16(d[mf][nf], af[0][mf], vb.x, vb.y);
                    mma_f16_k16(d[mf][nf], af[1][mf], vb.z, vb.w);
                }
            }
        }
    };

    // ---- mainloop: 2 k-tiles per super-iteration ----
    for (int S = 0; S < NKT; S += 2) {
        asm volatile("cp.async.wait_group 2;" ::: "memory");
        __syncthreads();

        if (S + 4 < NKT) { ISSUE_B(S + 4); }
        else { asm volatile("cp.async.commit_group;" ::: "memory"); }
        if (S + 5 < NKT) { ISSUE_B(S + 5); }
        else { asm volatile("cp.async.commit_group;" ::: "memory"); }

        compute_tile(S);
        compute_tile(S + 1);
    }

    // ---- epilogue: out = d + b2 ----
    float b2v[8][2];
#pragma unroll
    for (int nf = 0; nf < 8; nf++) {
        b2v[nf][0] = __ldg(b2 + n0 + nw + nf * 8 + fc * 2);
        b2v[nf][1] = __ldg(b2 + n0 + nw + nf * 8 + fc * 2 + 1);
    }
#pragma unroll
    for (int mf = 0; mf < 2; mf++) {
#pragma unroll
        for (int i2 = 0; i2 < 2; i2++) {
            const int row = m0 + mw + mf * 16 + fr + i2 * 8;
            float* orow = out + (size_t)row * E_DIM + n0 + nw + fc * 2;
#pragma unroll
            for (int nf = 0; nf < 8; nf++) {
                float2 v;
                v.x = d[mf][nf][i2 * 2 + 0] + b2v[nf][0];
                v.y = d[mf][nf][i2 * 2 + 1] + b2v[nf][1];
                *(float2*)(orow + nf * 8) = v;
            }
        }
    }
}

extern "C" void kernel_launch(void* const* d_in, const int* in_sizes, int n_in,
                              void* d_out, int out_size) {
    const float* x     = (const float*)d_in[0];
    const float* theta = (const float*)d_in[1];
    const float* W1    = (const float*)d_in[2];
    const float* b1    = (const float*)d_in[3];
    const float* W2    = (const float*)d_in[4];
    const float* b2    = (const float*)d_in[5];
    float* out = (float*)d_out;

    const int M = in_sizes[0] / E_DIM;   // 32768

    prep_kernel<<<(E_DIM * F_DIM + F_DIM * 8) / 256, 256>>>(W2, W1);

    cudaFuncSetAttribute(ffq_mma_kernel,
                         cudaFuncAttributeMaxDynamicSharedMemorySize, SMEM_BYTES);
    dim3 grid(E_DIM / BN, M / BM);
    ffq_mma_kernel<<<grid, NT, SMEM_BYTES>>>(x, theta, b1, b2, out);
}